// round 16
// baseline (speedup 1.0000x reference)
#include <cuda_runtime.h>
#include <cuda_fp16.h>
#include <math.h>
#include <stdint.h>

// Problem constants
#define T_LEN 512
#define NBATCH 64
#define HID 512
#define G4 2048          // 4*HID
#define NVOCAB 10000

#define SCAN_BLOCKS 128
#define SCAN_THREADS 256
#define NPAD 36          // red buffer row stride (floats)

// -------- device scratch --------
__device__ __align__(16) __half g_embh[(size_t)NVOCAB * 512]; // emb_table, fp16
__device__ __align__(16) __half g_wih0h[(size_t)G4 * 512];    // Wih0, fp16
__device__ __align__(16) __half g_E0h[(size_t)NVOCAB * G4];   // emb @ Wih0^T + b0 (fp16)
__device__ __align__(16) __half g_h0buf[2][NBATCH * HID];     // layer0 h ping-pong, frag layout
__device__ __align__(16) __half g_h1buf[2][NBATCH * HID];     // layer1 h ping-pong, frag layout
__device__ unsigned g_ctrs[2][64];                             // per-half barrier counters
__device__ int g_maxsl2[2];                                    // per-half max(sen_len)

// ---------------- helpers ----------------
__device__ __forceinline__ void mma_f16(float* c, const unsigned* a, const unsigned* b) {
    asm("mma.sync.aligned.m16n8k16.row.col.f32.f16.f16.f32 "
        "{%0,%1,%2,%3}, {%4,%5,%6,%7}, {%8,%9}, {%0,%1,%2,%3};"
        : "+f"(c[0]), "+f"(c[1]), "+f"(c[2]), "+f"(c[3])
        : "r"(a[0]), "r"(a[1]), "r"(a[2]), "r"(a[3]), "r"(b[0]), "r"(b[1]));
}
__device__ __forceinline__ unsigned ld_acq(const unsigned* p) {
    unsigned v; asm volatile("ld.acquire.gpu.global.u32 %0, [%1];" : "=r"(v) : "l"(p)); return v;
}
__device__ __forceinline__ void cp16(unsigned sdst, const void* gsrc) {
    asm volatile("cp.async.cg.shared.global [%0], [%1], 16;" :: "r"(sdst), "l"(gsrc));
}
__device__ __forceinline__ float tanh_ap(float x) {
    float y; asm("tanh.approx.f32 %0, %1;" : "=f"(y) : "f"(x)); return y;
}
// sigmoid via tanh: sig(x) = 0.5*tanh(x/2) + 0.5
__device__ __forceinline__ float sig_(float x) {
    return fmaf(0.5f, tanh_ap(0.5f * x), 0.5f);
}
// fp16 half-index for h value (batch b, unit k) in m16n8k16 A-fragment layout.
__device__ __forceinline__ int hidx16(int b, int k) {
    int kk = k >> 4, mt = b >> 4, r = b & 15, kl = k & 15;
    int lane = (r & 7) * 4 + ((kl & 7) >> 1);
    int w = ((kl >> 3) << 1) | (r >> 3);
    return (((kk * 4 + mt) * 32 + lane) * 4 + w) * 2 + (k & 1);
}

// ---------------------------------------------------------------------------
// fp32 -> fp16 conversion of emb_table and Wih0 (one pass, ~36 MB)
// ---------------------------------------------------------------------------
#define EMB4 ((NVOCAB * 512) / 4)        // 1,280,000 float4
#define W4   ((G4 * 512) / 4)            // 262,144 float4

__global__ void convert_fp16_kernel(const float* __restrict__ emb,
                                    const float* __restrict__ wih0) {
    int idx = blockIdx.x * blockDim.x + threadIdx.x;
    if (idx < EMB4) {
        float4 v = ((const float4*)emb)[idx];
        __half2* d = (__half2*)g_embh;
        d[idx * 2]     = __floats2half2_rn(v.x, v.y);
        d[idx * 2 + 1] = __floats2half2_rn(v.z, v.w);
    } else if (idx < EMB4 + W4) {
        int j = idx - EMB4;
        float4 v = ((const float4*)wih0)[j];
        __half2* d = (__half2*)g_wih0h;
        d[j * 2]     = __floats2half2_rn(v.x, v.y);
        d[j * 2 + 1] = __floats2half2_rn(v.z, v.w);
    }
}

// ---------------------------------------------------------------------------
__global__ void zero_init_kernel(const int* __restrict__ sen_len) {
    int i = blockIdx.x * blockDim.x + threadIdx.x;
    if (i < (NBATCH * HID)) {          // both parities (as u32)
        ((unsigned*)g_h0buf)[i] = 0u;
        ((unsigned*)g_h1buf)[i] = 0u;
    }
    if (i < 2 * 64) ((unsigned*)g_ctrs)[i] = 0u;
    if (i < 2) {
        int m = 1;
        for (int b = 0; b < 32; b++) m = max(m, sen_len[i * 32 + b]);
        g_maxsl2[i] = m;
    }
}

// ---------------------------------------------------------------------------
// fp16 tensor-core GEMM: g_E0h[M][2048] = Ah[M][512] @ Wh[2048][512]^T + (b1+b2)
// m16n8k16, BM=BN=128, BK=32, 256 threads (8 warps as 2x4), double-buffered.
// ---------------------------------------------------------------------------
#define HSTR 20
#define HBUF (128 * HSTR)

__global__ __launch_bounds__(256, 2) void gemm_e0_kernel(
    const float* __restrict__ bi1,
    const float* __restrict__ bi2,
    int M)
{
    extern __shared__ unsigned gsm[];
    unsigned* As = gsm;                  // [2][HBUF]
    unsigned* Bs = gsm + 2 * HBUF;       // [2][HBUF]

    const __half* Ah = g_embh;
    const __half* Wh = g_wih0h;

    const int tid = threadIdx.x;
    const int lane = tid & 31;
    const int warp = tid >> 5;
    const int g = lane >> 2;
    const int tig = lane & 3;
    const int wm = warp & 1;
    const int wn = warp >> 1;
    const int m0 = blockIdx.y * 128;
    const int n0 = blockIdx.x * 128;

    float acc[4][4][4];
#pragma unroll
    for (int i = 0; i < 4; i++)
#pragma unroll
        for (int j = 0; j < 4; j++)
#pragma unroll
            for (int e = 0; e < 4; e++) acc[i][j][e] = 0.0f;

    int lrow[2], lch[2];
#pragma unroll
    for (int p = 0; p < 2; p++) {
        int id = tid + p * 256;
        lrow[p] = id >> 2;
        lch[p] = (id & 3) * 8;
    }

    {
#pragma unroll
        for (int p = 0; p < 2; p++) {
            int r = lrow[p], ch = lch[p];
            uint4 va = make_uint4(0u, 0u, 0u, 0u);
            if (m0 + r < M) va = *(const uint4*)(Ah + (size_t)(m0 + r) * 512 + ch);
            *(uint4*)(As + r * HSTR + ch / 2) = va;
            uint4 vb = *(const uint4*)(Wh + (size_t)(n0 + r) * 512 + ch);
            *(uint4*)(Bs + r * HSTR + ch / 2) = vb;
        }
    }
    __syncthreads();

    uint4 pa[2], pb[2];
    for (int it = 0; it < 16; it++) {
        int buf = it & 1;
        if (it < 15) {
            int k0 = (it + 1) * 32;
#pragma unroll
            for (int p = 0; p < 2; p++) {
                int r = lrow[p], ch = lch[p];
                pa[p] = make_uint4(0u, 0u, 0u, 0u);
                if (m0 + r < M) pa[p] = *(const uint4*)(Ah + (size_t)(m0 + r) * 512 + k0 + ch);
                pb[p] = *(const uint4*)(Wh + (size_t)(n0 + r) * 512 + k0 + ch);
            }
        }
        const unsigned* Ab = As + buf * HBUF;
        const unsigned* Bb = Bs + buf * HBUF;
#pragma unroll
        for (int kk = 0; kk < 2; kk++) {
            int kb = kk * 8;
            unsigned af[4][4];
#pragma unroll
            for (int mf = 0; mf < 4; mf++) {
                int r = wm * 64 + mf * 16 + g;
                af[mf][0] = Ab[r * HSTR + kb + tig];
                af[mf][1] = Ab[(r + 8) * HSTR + kb + tig];
                af[mf][2] = Ab[r * HSTR + kb + tig + 4];
                af[mf][3] = Ab[(r + 8) * HSTR + kb + tig + 4];
            }
            unsigned bf[4][2];
#pragma unroll
            for (int nf = 0; nf < 4; nf++) {
                int n = wn * 32 + nf * 8 + g;
                bf[nf][0] = Bb[n * HSTR + kb + tig];
                bf[nf][1] = Bb[n * HSTR + kb + tig + 4];
            }
#pragma unroll
            for (int mf = 0; mf < 4; mf++)
#pragma unroll
                for (int nf = 0; nf < 4; nf++)
                    mma_f16(acc[mf][nf], af[mf], bf[nf]);
        }
        if (it < 15) {
            unsigned* Ad = As + (buf ^ 1) * HBUF;
            unsigned* Bd = Bs + (buf ^ 1) * HBUF;
#pragma unroll
            for (int p = 0; p < 2; p++) {
                int r = lrow[p], ch = lch[p];
                *(uint4*)(Ad + r * HSTR + ch / 2) = pa[p];
                *(uint4*)(Bd + r * HSTR + ch / 2) = pb[p];
            }
        }
        __syncthreads();
    }

#pragma unroll
    for (int nf = 0; nf < 4; nf++) {
        int n = n0 + wn * 32 + nf * 8 + 2 * tig;
        float bb0 = bi1[n] + bi2[n];
        float bb1 = bi1[n + 1] + bi2[n + 1];
#pragma unroll
        for (int mf = 0; mf < 4; mf++) {
            int r = m0 + wm * 64 + mf * 16 + g;
            if (r < M) {
                __half2 v = __floats2half2_rn(acc[mf][nf][0] + bb0, acc[mf][nf][1] + bb1);
                *(__half2*)(g_E0h + (size_t)r * G4 + n) = v;
            }
            if (r + 8 < M) {
                __half2 v = __floats2half2_rn(acc[mf][nf][2] + bb0, acc[mf][nf][3] + bb1);
                *(__half2*)(g_E0h + (size_t)(r + 8) * G4 + n) = v;
            }
        }
    }
}

// ---------------------------------------------------------------------------
// Fused two-layer pipelined LSTM scan (R12/R15 structure) with
// OWN-BUFFER-FIRST mma ordering:
//   warp (ks,0) stages sh_h0 slice, warp (ks,1) stages sh_h1 slice;
//   each warp waits only for ITS OWN cp.async, runs the mma ops that read
//   its own buffer (ns=0: mma0+mmaI on sh_h0; ns=1: mmaU on sh_h1), then
//   crosses the pairwise bar and runs the ops on the partner's buffer.
//   The partner's L2 staging latency is hidden under the warp's own mma.
// fp32 accumulation order changes for ns=1's acc1 (mmaU first) — benign.
// ---------------------------------------------------------------------------
__global__ __launch_bounds__(SCAN_THREADS) void lstm_fused_kernel(
    const int* __restrict__ src,
    const float* __restrict__ Whh0,
    const float* __restrict__ Wih1,
    const float* __restrict__ Whh1,
    const float* __restrict__ bih1,
    const float* __restrict__ bhh1,
    const int* __restrict__ sen_len,
    float* __restrict__ final_out)
{
    extern __shared__ unsigned ssm[];
    unsigned* sh_h0 = ssm;                     // 8192 u32 = 32 KB fp16 (this half)
    unsigned* sh_h1 = ssm + 8192;              // 8192 u32
    float* red0 = (float*)(ssm + 16384);       // [4][32][NPAD]
    float* red1 = red0 + 4 * 32 * NPAD;

    const int tid = threadIdx.x;
    const int lane = tid & 31;
    const int warp = tid >> 5;       // 0..7
    const int ks = warp >> 1;        // k-slice [128ks, 128ks+128)
    const int ns = warp & 1;         // row half / staging owner
    const int g = lane >> 2;
    const int tig = lane & 3;
    const int ub = blockIdx.x >> 1;
    const int bh = blockIdx.x & 1;
    const int u0 = ub * 8;

    unsigned sh_base;
    asm("{ .reg .u64 t; cvta.to.shared.u64 t, %1; cvt.u32.u64 %0, t; }"
        : "=r"(sh_base) : "l"((void*)ssm));

    // ---- B fragments in registers (once): Whh0, Wih1, Whh1 ----
    unsigned breg0[8][2][2], bregI[8][2][2], bregU[8][2][2];
#pragma unroll
    for (int kkl = 0; kkl < 8; kkl++) {
#pragma unroll
        for (int nt = 0; nt < 2; nt++) {
            int n = ns * 16 + nt * 8 + g;
            size_t row = (size_t)((n & 3) * 512 + u0 + (n >> 2)) * 512
                       + ks * 128 + kkl * 16;
            {
                const float* wr = Whh0 + row;
                __half2 h0 = __floats2half2_rn(wr[2 * tig], wr[2 * tig + 1]);
                __half2 h1 = __floats2half2_rn(wr[2 * tig + 8], wr[2 * tig + 9]);
                breg0[kkl][nt][0] = *(unsigned*)&h0;
                breg0[kkl][nt][1] = *(unsigned*)&h1;
            }
            {
                const float* wr = Wih1 + row;
                __half2 h0 = __floats2half2_rn(wr[2 * tig], wr[2 * tig + 1]);
                __half2 h1 = __floats2half2_rn(wr[2 * tig + 8], wr[2 * tig + 9]);
                bregI[kkl][nt][0] = *(unsigned*)&h0;
                bregI[kkl][nt][1] = *(unsigned*)&h1;
            }
            {
                const float* wr = Whh1 + row;
                __half2 h0 = __floats2half2_rn(wr[2 * tig], wr[2 * tig + 1]);
                __half2 h1 = __floats2half2_rn(wr[2 * tig + 8], wr[2 * tig + 9]);
                bregU[kkl][nt][0] = *(unsigned*)&h0;
                bregU[kkl][nt][1] = *(unsigned*)&h1;
            }
        }
    }

    // ---- cell-phase mapping: thread = (unit u_loc, batch b_loc) ----
    const int u_loc = tid >> 5;          // 0..7
    const int b_loc = lane;              // 0..31
    const int b_glob = bh * 32 + b_loc;
    const int u_glob = u0 + u_loc;

    float bsum[4];
#pragma unroll
    for (int gt = 0; gt < 4; gt++)
        bsum[gt] = bih1[gt * 512 + u_glob] + bhh1[gt * 512 + u_glob];

    float c_l0 = 0.f, c_l1 = 0.f;
    const int sl = sen_len[b_glob];
    const int maxsl = g_maxsl2[bh];
    const int hi = hidx16(b_glob, u_glob);
    unsigned* ctr = &g_ctrs[bh][0];
    const int barid = 1 + ks;            // named barrier per warp pair

    // ---- initial E0 prefetch (t = 0) ----
    float p[4];
    {
        int r = src[b_glob];
        const __half* e = g_E0h + (size_t)r * G4 + u_glob;
#pragma unroll
        for (int gt = 0; gt < 4; gt++) p[gt] = __half2float(e[gt * 512]);
    }

    for (int t = 0; t <= maxsl; t++) {
        const bool do_l0 = (t < maxsl);
        const bool do_l1 = (t >= 1);

        // ---- stage own slice: (ks,0) -> h0[t-1]; (ks,1) -> h1[t-2] ----
        {
            const uint4* gs = (const uint4*)(ns == 0 ? g_h0buf[(t + 1) & 1]
                                                     : g_h1buf[t & 1]);
            unsigned dstbase = sh_base + (ns ? 32768u : 0u);
#pragma unroll
            for (int i = 0; i < 16; i++) {
                int kk = ks * 8 + (i >> 1);
                int io = i & 1;
                int gidx = (kk * 4 + 2 * bh + io) * 32 + lane;
                int didx = (kk * 2 + io) * 32 + lane;
                cp16(dstbase + (unsigned)didx * 16, gs + gidx);
            }
            asm volatile("cp.async.commit_group;");
        }

        // wait ONLY for own staging; partner's is needed after the bar
        asm volatile("cp.async.wait_group 0;" ::: "memory");

        // ---- mma: own-buffer ops first, then cross the pairwise bar ----
        {
            float acc0[2][2][4], acc1[2][2][4];
#pragma unroll
            for (int mt2 = 0; mt2 < 2; mt2++)
#pragma unroll
                for (int nt = 0; nt < 2; nt++)
#pragma unroll
                    for (int e = 0; e < 4; e++) { acc0[mt2][nt][e] = 0.f; acc1[mt2][nt][e] = 0.f; }

            if (ns == 0) {
                // own: sh_h0 -> mma0 + mmaI
#pragma unroll
                for (int kkl = 0; kkl < 8; kkl++) {
                    int base = (ks * 8 + kkl) * 2;
#pragma unroll
                    for (int mt2 = 0; mt2 < 2; mt2++) {
                        uint4 a0 = *(const uint4*)(sh_h0 + ((base + mt2) * 32 + lane) * 4);
                        mma_f16(acc0[mt2][0], (const unsigned*)&a0, breg0[kkl][0]);
                        mma_f16(acc0[mt2][1], (const unsigned*)&a0, breg0[kkl][1]);
                        mma_f16(acc1[mt2][0], (const unsigned*)&a0, bregI[kkl][0]);
                        mma_f16(acc1[mt2][1], (const unsigned*)&a0, bregI[kkl][1]);
                    }
                }
                asm volatile("bar.sync %0, 64;" :: "r"(barid) : "memory");
                // partner: sh_h1 -> mmaU
#pragma unroll
                for (int kkl = 0; kkl < 8; kkl++) {
                    int base = (ks * 8 + kkl) * 2;
#pragma unroll
                    for (int mt2 = 0; mt2 < 2; mt2++) {
                        uint4 a1 = *(const uint4*)(sh_h1 + ((base + mt2) * 32 + lane) * 4);
                        mma_f16(acc1[mt2][0], (const unsigned*)&a1, bregU[kkl][0]);
                        mma_f16(acc1[mt2][1], (const unsigned*)&a1, bregU[kkl][1]);
                    }
                }
            } else {
                // own: sh_h1 -> mmaU
#pragma unroll
                for (int kkl = 0; kkl < 8; kkl++) {
                    int base = (ks * 8 + kkl) * 2;
#pragma unroll
                    for (int mt2 = 0; mt2 < 2; mt2++) {
                        uint4 a1 = *(const uint4*)(sh_h1 + ((base + mt2) * 32 + lane) * 4);
                        mma_f16(acc1[mt2][0], (const unsigned*)&a1, bregU[kkl][0]);
                        mma_f16(acc1[mt2][1], (const unsigned*)&a1, bregU[kkl][1]);
                    }
                }
                asm volatile("bar.sync %0, 64;" :: "r"(barid) : "memory");
                // partner: sh_h0 -> mma0 + mmaI
#pragma unroll
                for (int kkl = 0; kkl < 8; kkl++) {
                    int base = (ks * 8 + kkl) * 2;
#pragma unroll
                    for (int mt2 = 0; mt2 < 2; mt2++) {
                        uint4 a0 = *(const uint4*)(sh_h0 + ((base + mt2) * 32 + lane) * 4);
                        mma_f16(acc0[mt2][0], (const unsigned*)&a0, breg0[kkl][0]);
                        mma_f16(acc0[mt2][1], (const unsigned*)&a0, breg0[kkl][1]);
                        mma_f16(acc1[mt2][0], (const unsigned*)&a0, bregI[kkl][0]);
                        mma_f16(acc1[mt2][1], (const unsigned*)&a0, bregI[kkl][1]);
                    }
                }
            }

            // ---- store k-partials: red[ks][m_loc][n] ----
#pragma unroll
            for (int mt2 = 0; mt2 < 2; mt2++)
#pragma unroll
                for (int nt = 0; nt < 2; nt++) {
                    int m_loc = mt2 * 16 + g;
                    int col = ns * 16 + nt * 8 + 2 * tig;
                    float* rp0 = &red0[(ks * 32 + m_loc) * NPAD + col];
                    *(float2*)rp0 = make_float2(acc0[mt2][nt][0], acc0[mt2][nt][1]);
                    *(float2*)(rp0 + 8 * NPAD) = make_float2(acc0[mt2][nt][2], acc0[mt2][nt][3]);
                    float* rp1 = &red1[(ks * 32 + m_loc) * NPAD + col];
                    *(float2*)rp1 = make_float2(acc1[mt2][nt][0], acc1[mt2][nt][1]);
                    *(float2*)(rp1 + 8 * NPAD) = make_float2(acc1[mt2][nt][2], acc1[mt2][nt][3]);
                }
        }
        __syncthreads();

        // ---- layer0 cell: h_l0[t] ----
        if (do_l0) {
            float z[4];
#pragma unroll
            for (int gt = 0; gt < 4; gt++) z[gt] = p[gt];
#pragma unroll
            for (int w = 0; w < 4; w++) {
                float4 v = *(const float4*)&red0[(w * 32 + b_loc) * NPAD + u_loc * 4];
                z[0] += v.x; z[1] += v.y; z[2] += v.z; z[3] += v.w;
            }
            float ig = sig_(z[0]), fg = sig_(z[1]), gg = tanh_ap(z[2]), og = sig_(z[3]);
            c_l0 = fg * c_l0 + ig * gg;
            float hn = og * tanh_ap(c_l0);
            g_h0buf[t & 1][hi] = __float2half_rn(hn);
        }

        // ---- layer1 cell: h_l1[t-1] ----
        if (do_l1) {
            float z[4];
#pragma unroll
            for (int gt = 0; gt < 4; gt++) z[gt] = bsum[gt];
#pragma unroll
            for (int w = 0; w < 4; w++) {
                float4 v = *(const float4*)&red1[(w * 32 + b_loc) * NPAD + u_loc * 4];
                z[0] += v.x; z[1] += v.y; z[2] += v.z; z[3] += v.w;
            }
            float ig = sig_(z[0]), fg = sig_(z[1]), gg = tanh_ap(z[2]), og = sig_(z[3]);
            c_l1 = fg * c_l1 + ig * gg;
            float hn = og * tanh_ap(c_l1);
            g_h1buf[(t - 1) & 1][hi] = __float2half_rn(hn);
            if (t == sl) final_out[b_glob * HID + u_glob] = hn;
        }

        // ---- grid barrier (per-half counter) + E0 prefetch overlap ----
        __syncthreads();   // all h stores issued block-wide
        if (tid == 0) {
            asm volatile("red.release.gpu.global.add.u32 [%0], 1;"
                         :: "l"(ctr) : "memory");
        }
        // prefetch E0 for step t+1 while tid0 polls (independent of h)
        {
            int tt = (t + 1 < maxsl) ? (t + 1) : 0;
            int r = src[tt * NBATCH + b_glob];
            const __half* e = g_E0h + (size_t)r * G4 + u_glob;
#pragma unroll
            for (int gt = 0; gt < 4; gt++) p[gt] = __half2float(e[gt * 512]);
        }
        if (tid == 0) {
            unsigned tgt = 64u * (unsigned)(t + 1);
            while (ld_acq(ctr) < tgt) { }
        }
        __syncthreads();
    }
}

// ---------------------------------------------------------------------------
extern "C" void kernel_launch(void* const* d_in, const int* in_sizes, int n_in,
                              void* d_out, int out_size)
{
    const int*   src       = (const int*)  d_in[0];
    const int*   sen_len   = (const int*)  d_in[1];
    const float* emb_table = (const float*)d_in[2];
    const float* Wih0      = (const float*)d_in[3];
    const float* Whh0      = (const float*)d_in[4];
    const float* bih0      = (const float*)d_in[5];
    const float* bhh0      = (const float*)d_in[6];
    const float* Wih1      = (const float*)d_in[7];
    const float* Whh1      = (const float*)d_in[8];
    const float* bih1      = (const float*)d_in[9];
    const float* bhh1      = (const float*)d_in[10];
    float* out = (float*)d_out;

    const size_t gemm_smem = (size_t)4 * HBUF * sizeof(unsigned);        // 40960 B
    const size_t scan_smem =
        (size_t)(16384 + 2 * 4 * 32 * NPAD) * sizeof(unsigned);          // 102400 B
    cudaFuncSetAttribute(gemm_e0_kernel,
                         cudaFuncAttributeMaxDynamicSharedMemorySize, (int)gemm_smem);
    cudaFuncSetAttribute(lstm_fused_kernel,
                         cudaFuncAttributeMaxDynamicSharedMemorySize, (int)scan_smem);

    // Phase -1: convert emb_table + Wih0 to fp16
    {
        int total = EMB4 + W4;
        convert_fp16_kernel<<<(total + 255) / 256, 256>>>(emb_table, Wih0);
    }

    // Phase 0: E0 = emb_table @ Wih0^T + (bih0+bhh0)   (10000 x 2048, fp16 in/out)
    {
        dim3 grid(G4 / 128, (NVOCAB + 127) / 128);
        gemm_e0_kernel<<<grid, 256, gemm_smem>>>(bih0, bhh0, NVOCAB);
    }

    // Phase 1: fused two-layer pipelined scan, decoupled batch halves
    zero_init_kernel<<<128, 512>>>(sen_len);
    lstm_fused_kernel<<<SCAN_BLOCKS, SCAN_THREADS, scan_smem>>>(
        src, Whh0, Wih1, Whh1, bih1, bhh1, sen_len, out);
}

// round 17
// speedup vs baseline: 1.0554x; 1.0554x over previous
#include <cuda_runtime.h>
#include <cuda_fp16.h>
#include <math.h>
#include <stdint.h>

// Problem constants
#define T_LEN 512
#define NBATCH 64
#define HID 512
#define G4 2048          // 4*HID
#define NVOCAB 10000

#define SCAN_BLOCKS 128
#define SCAN_THREADS 256
#define NPAD 36          // red buffer row stride (floats)

// -------- device scratch --------
__device__ __align__(16) __half g_embh[(size_t)NVOCAB * 512]; // emb_table, fp16
__device__ __align__(16) __half g_wih0h[(size_t)G4 * 512];    // Wih0, fp16
__device__ __align__(16) __half g_E0h[(size_t)NVOCAB * G4];   // emb @ Wih0^T + b0 (fp16)
__device__ __align__(16) __half g_h0buf[2][NBATCH * HID];     // layer0 h ping-pong, frag layout
__device__ __align__(16) __half g_h1buf[2][NBATCH * HID];     // layer1 h ping-pong, frag layout
__device__ unsigned g_ctrs[2][64];                             // per-half barrier counters
__device__ int g_maxsl2[2];                                    // per-half max(sen_len)

// ---------------- helpers ----------------
__device__ __forceinline__ void mma_f16(float* c, const unsigned* a, const unsigned* b) {
    asm("mma.sync.aligned.m16n8k16.row.col.f32.f16.f16.f32 "
        "{%0,%1,%2,%3}, {%4,%5,%6,%7}, {%8,%9}, {%0,%1,%2,%3};"
        : "+f"(c[0]), "+f"(c[1]), "+f"(c[2]), "+f"(c[3])
        : "r"(a[0]), "r"(a[1]), "r"(a[2]), "r"(a[3]), "r"(b[0]), "r"(b[1]));
}
__device__ __forceinline__ unsigned ld_acq(const unsigned* p) {
    unsigned v; asm volatile("ld.acquire.gpu.global.u32 %0, [%1];" : "=r"(v) : "l"(p)); return v;
}
__device__ __forceinline__ void cp16(unsigned sdst, const void* gsrc) {
    asm volatile("cp.async.cg.shared.global [%0], [%1], 16;" :: "r"(sdst), "l"(gsrc));
}
__device__ __forceinline__ float tanh_ap(float x) {
    float y; asm("tanh.approx.f32 %0, %1;" : "=f"(y) : "f"(x)); return y;
}
// sigmoid via tanh: sig(x) = 0.5*tanh(x/2) + 0.5
__device__ __forceinline__ float sig_(float x) {
    return fmaf(0.5f, tanh_ap(0.5f * x), 0.5f);
}
// fp16 half-index for h value (batch b, unit k) in m16n8k16 A-fragment layout.
__device__ __forceinline__ int hidx16(int b, int k) {
    int kk = k >> 4, mt = b >> 4, r = b & 15, kl = k & 15;
    int lane = (r & 7) * 4 + ((kl & 7) >> 1);
    int w = ((kl >> 3) << 1) | (r >> 3);
    return (((kk * 4 + mt) * 32 + lane) * 4 + w) * 2 + (k & 1);
}

// ---------------------------------------------------------------------------
// fp32 -> fp16 conversion of emb_table and Wih0 (one pass, ~36 MB)
// ---------------------------------------------------------------------------
#define EMB4 ((NVOCAB * 512) / 4)        // 1,280,000 float4
#define W4   ((G4 * 512) / 4)            // 262,144 float4

__global__ void convert_fp16_kernel(const float* __restrict__ emb,
                                    const float* __restrict__ wih0) {
    int idx = blockIdx.x * blockDim.x + threadIdx.x;
    if (idx < EMB4) {
        float4 v = ((const float4*)emb)[idx];
        __half2* d = (__half2*)g_embh;
        d[idx * 2]     = __floats2half2_rn(v.x, v.y);
        d[idx * 2 + 1] = __floats2half2_rn(v.z, v.w);
    } else if (idx < EMB4 + W4) {
        int j = idx - EMB4;
        float4 v = ((const float4*)wih0)[j];
        __half2* d = (__half2*)g_wih0h;
        d[j * 2]     = __floats2half2_rn(v.x, v.y);
        d[j * 2 + 1] = __floats2half2_rn(v.z, v.w);
    }
}

// ---------------------------------------------------------------------------
__global__ void zero_init_kernel(const int* __restrict__ sen_len) {
    int i = blockIdx.x * blockDim.x + threadIdx.x;
    if (i < (NBATCH * HID)) {          // both parities (as u32)
        ((unsigned*)g_h0buf)[i] = 0u;
        ((unsigned*)g_h1buf)[i] = 0u;
    }
    if (i < 2 * 64) ((unsigned*)g_ctrs)[i] = 0u;
    if (i < 2) {
        int m = 1;
        for (int b = 0; b < 32; b++) m = max(m, sen_len[i * 32 + b]);
        g_maxsl2[i] = m;
    }
}

// ---------------------------------------------------------------------------
// fp16 tensor-core GEMM: g_E0h[M][2048] = Ah[M][512] @ Wh[2048][512]^T + (b1+b2)
// m16n8k16, BM=BN=128, BK=32, 256 threads (8 warps as 2x4), double-buffered.
// smem rows stored as u32 (half2 k-pairs), stride HSTR=20 (conflict-free).
// ---------------------------------------------------------------------------
#define HSTR 20
#define HBUF (128 * HSTR)

__global__ __launch_bounds__(256, 2) void gemm_e0_kernel(
    const float* __restrict__ bi1,
    const float* __restrict__ bi2,
    int M)
{
    extern __shared__ unsigned gsm[];
    unsigned* As = gsm;                  // [2][HBUF]
    unsigned* Bs = gsm + 2 * HBUF;       // [2][HBUF]

    const __half* Ah = g_embh;
    const __half* Wh = g_wih0h;

    const int tid = threadIdx.x;
    const int lane = tid & 31;
    const int warp = tid >> 5;
    const int g = lane >> 2;
    const int tig = lane & 3;
    const int wm = warp & 1;
    const int wn = warp >> 1;
    const int m0 = blockIdx.y * 128;
    const int n0 = blockIdx.x * 128;

    float acc[4][4][4];
#pragma unroll
    for (int i = 0; i < 4; i++)
#pragma unroll
        for (int j = 0; j < 4; j++)
#pragma unroll
            for (int e = 0; e < 4; e++) acc[i][j][e] = 0.0f;

    // loader map: 512 uint4 per matrix per tile; 2 per thread
    int lrow[2], lch[2];
#pragma unroll
    for (int p = 0; p < 2; p++) {
        int id = tid + p * 256;
        lrow[p] = id >> 2;               // 0..127
        lch[p] = (id & 3) * 8;           // half offset within BK=32
    }

    // tile 0
    {
#pragma unroll
        for (int p = 0; p < 2; p++) {
            int r = lrow[p], ch = lch[p];
            uint4 va = make_uint4(0u, 0u, 0u, 0u);
            if (m0 + r < M) va = *(const uint4*)(Ah + (size_t)(m0 + r) * 512 + ch);
            *(uint4*)(As + r * HSTR + ch / 2) = va;
            uint4 vb = *(const uint4*)(Wh + (size_t)(n0 + r) * 512 + ch);
            *(uint4*)(Bs + r * HSTR + ch / 2) = vb;
        }
    }
    __syncthreads();

    uint4 pa[2], pb[2];
    for (int it = 0; it < 16; it++) {
        int buf = it & 1;
        if (it < 15) {
            int k0 = (it + 1) * 32;
#pragma unroll
            for (int p = 0; p < 2; p++) {
                int r = lrow[p], ch = lch[p];
                pa[p] = make_uint4(0u, 0u, 0u, 0u);
                if (m0 + r < M) pa[p] = *(const uint4*)(Ah + (size_t)(m0 + r) * 512 + k0 + ch);
                pb[p] = *(const uint4*)(Wh + (size_t)(n0 + r) * 512 + k0 + ch);
            }
        }
        const unsigned* Ab = As + buf * HBUF;
        const unsigned* Bb = Bs + buf * HBUF;
#pragma unroll
        for (int kk = 0; kk < 2; kk++) {
            int kb = kk * 8;
            unsigned af[4][4];
#pragma unroll
            for (int mf = 0; mf < 4; mf++) {
                int r = wm * 64 + mf * 16 + g;
                af[mf][0] = Ab[r * HSTR + kb + tig];
                af[mf][1] = Ab[(r + 8) * HSTR + kb + tig];
                af[mf][2] = Ab[r * HSTR + kb + tig + 4];
                af[mf][3] = Ab[(r + 8) * HSTR + kb + tig + 4];
            }
            unsigned bf[4][2];
#pragma unroll
            for (int nf = 0; nf < 4; nf++) {
                int n = wn * 32 + nf * 8 + g;
                bf[nf][0] = Bb[n * HSTR + kb + tig];
                bf[nf][1] = Bb[n * HSTR + kb + tig + 4];
            }
#pragma unroll
            for (int mf = 0; mf < 4; mf++)
#pragma unroll
                for (int nf = 0; nf < 4; nf++)
                    mma_f16(acc[mf][nf], af[mf], bf[nf]);
        }
        if (it < 15) {
            unsigned* Ad = As + (buf ^ 1) * HBUF;
            unsigned* Bd = Bs + (buf ^ 1) * HBUF;
#pragma unroll
            for (int p = 0; p < 2; p++) {
                int r = lrow[p], ch = lch[p];
                *(uint4*)(Ad + r * HSTR + ch / 2) = pa[p];
                *(uint4*)(Bd + r * HSTR + ch / 2) = pb[p];
            }
        }
        __syncthreads();
    }

#pragma unroll
    for (int nf = 0; nf < 4; nf++) {
        int n = n0 + wn * 32 + nf * 8 + 2 * tig;
        float bb0 = bi1[n] + bi2[n];
        float bb1 = bi1[n + 1] + bi2[n + 1];
#pragma unroll
        for (int mf = 0; mf < 4; mf++) {
            int r = m0 + wm * 64 + mf * 16 + g;
            if (r < M) {
                __half2 v = __floats2half2_rn(acc[mf][nf][0] + bb0, acc[mf][nf][1] + bb1);
                *(__half2*)(g_E0h + (size_t)r * G4 + n) = v;
            }
            if (r + 8 < M) {
                __half2 v = __floats2half2_rn(acc[mf][nf][2] + bb0, acc[mf][nf][3] + bb1);
                *(__half2*)(g_E0h + (size_t)(r + 8) * G4 + n) = v;
            }
        }
    }
}

// ---------------------------------------------------------------------------
// Fused two-layer pipelined LSTM scan (final, R15-proven).
// 128 CTAs x 256 threads. Block (ub = bid>>1, bh = bid&1) owns units
// [8ub,8ub+8) x batches [32bh,32bh+32). Two independent batch-half groups
// (own counter + bound). Warp w: ks = w>>1 (k-slice 128), ns = w&1.
// Per step t: stage h0[t-1] + h1[t-2] (warp pair splits, pairwise named
// barrier), 3 fused m32xn16xk128 f16 mmas (symmetric across warps), smem
// k-reduction, both cells, single end-of-step per-half grid barrier with
// the E0 gather for t+1 overlapped into the poll window.
// ---------------------------------------------------------------------------
__global__ __launch_bounds__(SCAN_THREADS) void lstm_fused_kernel(
    const int* __restrict__ src,
    const float* __restrict__ Whh0,
    const float* __restrict__ Wih1,
    const float* __restrict__ Whh1,
    const float* __restrict__ bih1,
    const float* __restrict__ bhh1,
    const int* __restrict__ sen_len,
    float* __restrict__ final_out)
{
    extern __shared__ unsigned ssm[];
    unsigned* sh_h0 = ssm;                     // 8192 u32 = 32 KB fp16 (this half)
    unsigned* sh_h1 = ssm + 8192;              // 8192 u32
    float* red0 = (float*)(ssm + 16384);       // [4][32][NPAD]
    float* red1 = red0 + 4 * 32 * NPAD;

    const int tid = threadIdx.x;
    const int lane = tid & 31;
    const int warp = tid >> 5;       // 0..7
    const int ks = warp >> 1;        // k-slice [128ks, 128ks+128)
    const int ns = warp & 1;         // row half
    const int g = lane >> 2;
    const int tig = lane & 3;
    const int ub = blockIdx.x >> 1;
    const int bh = blockIdx.x & 1;
    const int u0 = ub * 8;

    unsigned sh_base;
    asm("{ .reg .u64 t; cvta.to.shared.u64 t, %1; cvt.u32.u64 %0, t; }"
        : "=r"(sh_base) : "l"((void*)ssm));

    // ---- B fragments in registers (once): Whh0, Wih1, Whh1 ----
    unsigned breg0[8][2][2], bregI[8][2][2], bregU[8][2][2];
#pragma unroll
    for (int kkl = 0; kkl < 8; kkl++) {
#pragma unroll
        for (int nt = 0; nt < 2; nt++) {
            int n = ns * 16 + nt * 8 + g;
            size_t row = (size_t)((n & 3) * 512 + u0 + (n >> 2)) * 512
                       + ks * 128 + kkl * 16;
            {
                const float* wr = Whh0 + row;
                __half2 h0 = __floats2half2_rn(wr[2 * tig], wr[2 * tig + 1]);
                __half2 h1 = __floats2half2_rn(wr[2 * tig + 8], wr[2 * tig + 9]);
                breg0[kkl][nt][0] = *(unsigned*)&h0;
                breg0[kkl][nt][1] = *(unsigned*)&h1;
            }
            {
                const float* wr = Wih1 + row;
                __half2 h0 = __floats2half2_rn(wr[2 * tig], wr[2 * tig + 1]);
                __half2 h1 = __floats2half2_rn(wr[2 * tig + 8], wr[2 * tig + 9]);
                bregI[kkl][nt][0] = *(unsigned*)&h0;
                bregI[kkl][nt][1] = *(unsigned*)&h1;
            }
            {
                const float* wr = Whh1 + row;
                __half2 h0 = __floats2half2_rn(wr[2 * tig], wr[2 * tig + 1]);
                __half2 h1 = __floats2half2_rn(wr[2 * tig + 8], wr[2 * tig + 9]);
                bregU[kkl][nt][0] = *(unsigned*)&h0;
                bregU[kkl][nt][1] = *(unsigned*)&h1;
            }
        }
    }

    // ---- cell-phase mapping: thread = (unit u_loc, batch b_loc) ----
    const int u_loc = tid >> 5;          // 0..7
    const int b_loc = lane;              // 0..31
    const int b_glob = bh * 32 + b_loc;
    const int u_glob = u0 + u_loc;

    float bsum[4];
#pragma unroll
    for (int gt = 0; gt < 4; gt++)
        bsum[gt] = bih1[gt * 512 + u_glob] + bhh1[gt * 512 + u_glob];

    float c_l0 = 0.f, c_l1 = 0.f;
    const int sl = sen_len[b_glob];
    const int maxsl = g_maxsl2[bh];
    const int hi = hidx16(b_glob, u_glob);
    unsigned* ctr = &g_ctrs[bh][0];
    const int barid = 1 + ks;            // named barrier per warp pair

    // ---- initial E0 prefetch (t = 0) ----
    float p[4];
    {
        int r = src[b_glob];
        const __half* e = g_E0h + (size_t)r * G4 + u_glob;
#pragma unroll
        for (int gt = 0; gt < 4; gt++) p[gt] = __half2float(e[gt * 512]);
    }

    for (int t = 0; t <= maxsl; t++) {
        const bool do_l0 = (t < maxsl);
        const bool do_l1 = (t >= 1);

        // ---- stage: warp (ks,0) -> h0[t-1] slice; (ks,1) -> h1[t-2] slice ----
        {
            const uint4* gs = (const uint4*)(ns == 0 ? g_h0buf[(t + 1) & 1]
                                                     : g_h1buf[t & 1]);
            unsigned dstbase = sh_base + (ns ? 32768u : 0u);
#pragma unroll
            for (int i = 0; i < 16; i++) {
                int kk = ks * 8 + (i >> 1);
                int io = i & 1;
                int gidx = (kk * 4 + 2 * bh + io) * 32 + lane;
                int didx = (kk * 2 + io) * 32 + lane;
                cp16(dstbase + (unsigned)didx * 16, gs + gidx);
            }
            asm volatile("cp.async.commit_group;");
        }

        asm volatile("cp.async.wait_group 0;" ::: "memory");
        // pairwise sync: warps (ks,0),(ks,1) exchange their staged slices
        asm volatile("bar.sync %0, 64;" :: "r"(barid) : "memory");

        // ---- mma: 3 GEMMs, m32 x n16 x k128 per warp (symmetric) ----
        {
            float acc0[2][2][4], acc1[2][2][4];
#pragma unroll
            for (int mt2 = 0; mt2 < 2; mt2++)
#pragma unroll
                for (int nt = 0; nt < 2; nt++)
#pragma unroll
                    for (int e = 0; e < 4; e++) { acc0[mt2][nt][e] = 0.f; acc1[mt2][nt][e] = 0.f; }

#pragma unroll
            for (int kkl = 0; kkl < 8; kkl++) {
                int base = (ks * 8 + kkl) * 2;
#pragma unroll
                for (int mt2 = 0; mt2 < 2; mt2++) {
                    uint4 a0 = *(const uint4*)(sh_h0 + ((base + mt2) * 32 + lane) * 4);
                    mma_f16(acc0[mt2][0], (const unsigned*)&a0, breg0[kkl][0]);
                    mma_f16(acc0[mt2][1], (const unsigned*)&a0, breg0[kkl][1]);
                    mma_f16(acc1[mt2][0], (const unsigned*)&a0, bregI[kkl][0]);
                    mma_f16(acc1[mt2][1], (const unsigned*)&a0, bregI[kkl][1]);
                    uint4 a1 = *(const uint4*)(sh_h1 + ((base + mt2) * 32 + lane) * 4);
                    mma_f16(acc1[mt2][0], (const unsigned*)&a1, bregU[kkl][0]);
                    mma_f16(acc1[mt2][1], (const unsigned*)&a1, bregU[kkl][1]);
                }
            }

            // ---- store k-partials: red[ks][m_loc][n] ----
#pragma unroll
            for (int mt2 = 0; mt2 < 2; mt2++)
#pragma unroll
                for (int nt = 0; nt < 2; nt++) {
                    int m_loc = mt2 * 16 + g;
                    int col = ns * 16 + nt * 8 + 2 * tig;
                    float* rp0 = &red0[(ks * 32 + m_loc) * NPAD + col];
                    *(float2*)rp0 = make_float2(acc0[mt2][nt][0], acc0[mt2][nt][1]);
                    *(float2*)(rp0 + 8 * NPAD) = make_float2(acc0[mt2][nt][2], acc0[mt2][nt][3]);
                    float* rp1 = &red1[(ks * 32 + m_loc) * NPAD + col];
                    *(float2*)rp1 = make_float2(acc1[mt2][nt][0], acc1[mt2][nt][1]);
                    *(float2*)(rp1 + 8 * NPAD) = make_float2(acc1[mt2][nt][2], acc1[mt2][nt][3]);
                }
        }
        __syncthreads();

        // ---- layer0 cell: h_l0[t] ----
        if (do_l0) {
            float z[4];
#pragma unroll
            for (int gt = 0; gt < 4; gt++) z[gt] = p[gt];
#pragma unroll
            for (int w = 0; w < 4; w++) {
                float4 v = *(const float4*)&red0[(w * 32 + b_loc) * NPAD + u_loc * 4];
                z[0] += v.x; z[1] += v.y; z[2] += v.z; z[3] += v.w;
            }
            float ig = sig_(z[0]), fg = sig_(z[1]), gg = tanh_ap(z[2]), og = sig_(z[3]);
            c_l0 = fg * c_l0 + ig * gg;
            float hn = og * tanh_ap(c_l0);
            g_h0buf[t & 1][hi] = __float2half_rn(hn);
        }

        // ---- layer1 cell: h_l1[t-1] ----
        if (do_l1) {
            float z[4];
#pragma unroll
            for (int gt = 0; gt < 4; gt++) z[gt] = bsum[gt];
#pragma unroll
            for (int w = 0; w < 4; w++) {
                float4 v = *(const float4*)&red1[(w * 32 + b_loc) * NPAD + u_loc * 4];
                z[0] += v.x; z[1] += v.y; z[2] += v.z; z[3] += v.w;
            }
            float ig = sig_(z[0]), fg = sig_(z[1]), gg = tanh_ap(z[2]), og = sig_(z[3]);
            c_l1 = fg * c_l1 + ig * gg;
            float hn = og * tanh_ap(c_l1);
            g_h1buf[(t - 1) & 1][hi] = __float2half_rn(hn);
            if (t == sl) final_out[b_glob * HID + u_glob] = hn;
        }

        // ---- grid barrier (per-half counter) + E0 prefetch overlap ----
        __syncthreads();   // all h stores issued block-wide
        if (tid == 0) {
            asm volatile("red.release.gpu.global.add.u32 [%0], 1;"
                         :: "l"(ctr) : "memory");
        }
        // prefetch E0 for step t+1 while tid0 polls (independent of h)
        {
            int tt = (t + 1 < maxsl) ? (t + 1) : 0;
            int r = src[tt * NBATCH + b_glob];
            const __half* e = g_E0h + (size_t)r * G4 + u_glob;
#pragma unroll
            for (int gt = 0; gt < 4; gt++) p[gt] = __half2float(e[gt * 512]);
        }
        if (tid == 0) {
            unsigned tgt = 64u * (unsigned)(t + 1);
            while (ld_acq(ctr) < tgt) { }
        }
        __syncthreads();
    }
}

// ---------------------------------------------------------------------------
extern "C" void kernel_launch(void* const* d_in, const int* in_sizes, int n_in,
                              void* d_out, int out_size)
{
    const int*   src       = (const int*)  d_in[0];
    const int*   sen_len   = (const int*)  d_in[1];
    const float* emb_table = (const float*)d_in[2];
    const float* Wih0      = (const float*)d_in[3];
    const float* Whh0      = (const float*)d_in[4];
    const float* bih0      = (const float*)d_in[5];
    const float* bhh0      = (const float*)d_in[6];
    const float* Wih1      = (const float*)d_in[7];
    const float* Whh1      = (const float*)d_in[8];
    const float* bih1      = (const float*)d_in[9];
    const float* bhh1      = (const float*)d_in[10];
    float* out = (float*)d_out;

    const size_t gemm_smem = (size_t)4 * HBUF * sizeof(unsigned);        // 40960 B
    const size_t scan_smem =
        (size_t)(16384 + 2 * 4 * 32 * NPAD) * sizeof(unsigned);          // 102400 B
    cudaFuncSetAttribute(gemm_e0_kernel,
                         cudaFuncAttributeMaxDynamicSharedMemorySize, (int)gemm_smem);
    cudaFuncSetAttribute(lstm_fused_kernel,
                         cudaFuncAttributeMaxDynamicSharedMemorySize, (int)scan_smem);

    // Phase -1: convert emb_table + Wih0 to fp16
    {
        int total = EMB4 + W4;
        convert_fp16_kernel<<<(total + 255) / 256, 256>>>(emb_table, Wih0);
    }

    // Phase 0: E0 = emb_table @ Wih0^T + (bih0+bhh0)   (10000 x 2048, fp16 in/out)
    {
        dim3 grid(G4 / 128, (NVOCAB + 127) / 128);
        gemm_e0_kernel<<<grid, 256, gemm_smem>>>(bih0, bhh0, NVOCAB);
    }

    // Phase 1: fused two-layer pipelined scan, decoupled batch halves
    zero_init_kernel<<<128, 512>>>(sen_len);
    lstm_fused_kernel<<<SCAN_BLOCKS, SCAN_THREADS, scan_smem>>>(
        src, Whh0, Wih1, Whh1, bih1, bhh1, sen_len, out);
}